// round 1
// baseline (speedup 1.0000x reference)
#include <cuda_runtime.h>
#include <stdint.h>

#define NTOK 16384
#define DDIM 512
#define HDIM 2048
#define NEXP 8
#define NPAIR (NTOK * 2)

// ---------------- device scratch (allocation-free) ----------------
__device__ int g_count[NEXP];
__device__ int g_i64;
__device__ int g_list[NEXP * NTOK];          // entries: token*2 + slot
__device__ unsigned char g_v1[NTOK];         // slot-1 valid (e1 != e0)
__device__ float g_h[(size_t)NPAIR * HDIM];  // 256 MiB intermediate
__device__ float g_y[(size_t)NPAIR * DDIM];  // 64 MiB per-pair outputs

// ---------------- routing ----------------
__global__ void prep_kernel(const int* __restrict__ aw) {
    __shared__ int nz;
    if (threadIdx.x == 0) nz = 0;
    __syncthreads();
    // Detect int64 vs int32 assign: if int64 (values 0..7), odd words are 0.
    if (threadIdx.x < 64) {
        if (aw[2 * threadIdx.x + 1] != 0) atomicOr(&nz, 1);
    }
    __syncthreads();
    if (threadIdx.x < NEXP) g_count[threadIdx.x] = 0;
    if (threadIdx.x == 0) g_i64 = (nz == 0) ? 1 : 0;
}

__global__ void route_kernel(const int* __restrict__ aw) {
    int t = blockIdx.x * blockDim.x + threadIdx.x;
    if (t >= NTOK) return;
    int e0, e1;
    if (g_i64) { e0 = aw[4 * t]; e1 = aw[4 * t + 2]; }
    else       { e0 = aw[2 * t]; e1 = aw[2 * t + 1]; }
    int p = atomicAdd(&g_count[e0], 1);
    g_list[e0 * NTOK + p] = 2 * t;
    int v1 = (e1 != e0) ? 1 : 0;
    g_v1[t] = (unsigned char)v1;
    if (v1) {
        p = atomicAdd(&g_count[e1], 1);
        g_list[e1 * NTOK + p] = 2 * t + 1;
    }
}

// ---------------- packed f32x2 helpers ----------------
__device__ __forceinline__ unsigned long long pack2(float x) {
    unsigned long long r;
    asm("mov.b64 %0, {%1, %1};" : "=l"(r) : "f"(x));
    return r;
}
__device__ __forceinline__ void fma2(unsigned long long& d,
                                     unsigned long long a,
                                     unsigned long long b) {
    asm("fma.rn.f32x2 %0, %1, %2, %0;" : "+l"(d) : "l"(a), "l"(b));
}
__device__ __forceinline__ float2 unpack2(unsigned long long v) {
    float2 r;
    asm("mov.b64 {%0, %1}, %2;" : "=f"(r.x), "=f"(r.y) : "l"(v));
    return r;
}

// ---------------- gather GEMM ----------------
// MODE 1: h[entry] = relu( x[entry>>1] @ W1[e] + b1[e] )   (K=512,  N=2048)
// MODE 2: y[entry] =       h[entry]    @ W2[e] + b2[e]     (K=2048, N=512)
#define BM 128
#define BN 128
#define BKK 8
#define TM 8
#define TN 8

template <int MODE>
__global__ __launch_bounds__(256)
void moe_gemm(const float* __restrict__ X,
              const float* __restrict__ Wall,
              const float* __restrict__ Biasall) {
    constexpr int KD = (MODE == 1) ? DDIM : HDIM;
    constexpr int ND = (MODE == 1) ? HDIM : DDIM;

    const int e = blockIdx.z;
    const int count = g_count[e];
    const int m0 = blockIdx.y * BM;
    if (m0 >= count) return;
    const int n0 = blockIdx.x * BN;

    const float* __restrict__ W    = Wall + (size_t)e * KD * ND;
    const float* __restrict__ bias = Biasall + e * ND;
    const int*   __restrict__ list = g_list + e * NTOK;

    __shared__ float As[BKK][BM];
    __shared__ float Bs[BKK][BN];

    const int tid = threadIdx.x;
    const int tr = tid >> 4;   // 0..15
    const int tc = tid & 15;   // 0..15

    // A gather: each thread owns one (row, 4-col) chunk per k-stage
    const int arow = tid >> 1;        // 0..127
    const int acol = (tid & 1) * 4;   // 0 or 4
    const int gm = m0 + arow;
    const int entry = list[(gm < count) ? gm : m0];  // safe fallback row
    const float* __restrict__ Arow;
    if (MODE == 1) Arow = X + (size_t)(entry >> 1) * DDIM;
    else           Arow = g_h + (size_t)entry * HDIM;

    const int brow = tid >> 5;         // 0..7
    const int bcol = (tid & 31) * 4;   // 0..124
    const float* __restrict__ Bptr = W + (size_t)brow * ND + n0 + bcol;

    unsigned long long acc[TM][TN / 2];
#pragma unroll
    for (int i = 0; i < TM; i++)
#pragma unroll
        for (int j = 0; j < TN / 2; j++) acc[i][j] = 0ull;

    for (int k0 = 0; k0 < KD; k0 += BKK) {
        float4 av = *(const float4*)(Arow + k0 + acol);
        float4 bv = *(const float4*)(Bptr + (size_t)k0 * ND);
        As[acol + 0][arow] = av.x;
        As[acol + 1][arow] = av.y;
        As[acol + 2][arow] = av.z;
        As[acol + 3][arow] = av.w;
        *(float4*)&Bs[brow][bcol] = bv;
        __syncthreads();

#pragma unroll
        for (int kk = 0; kk < BKK; kk++) {
            float4 a0 = *(const float4*)&As[kk][tr * TM];
            float4 a1 = *(const float4*)&As[kk][tr * TM + 4];
            const unsigned long long* bp =
                (const unsigned long long*)&Bs[kk][tc * TN];
            unsigned long long b0 = bp[0], b1 = bp[1], b2 = bp[2], b3 = bp[3];
            unsigned long long ap[TM];
            ap[0] = pack2(a0.x); ap[1] = pack2(a0.y);
            ap[2] = pack2(a0.z); ap[3] = pack2(a0.w);
            ap[4] = pack2(a1.x); ap[5] = pack2(a1.y);
            ap[6] = pack2(a1.z); ap[7] = pack2(a1.w);
#pragma unroll
            for (int i = 0; i < TM; i++) {
                fma2(acc[i][0], ap[i], b0);
                fma2(acc[i][1], ap[i], b1);
                fma2(acc[i][2], ap[i], b2);
                fma2(acc[i][3], ap[i], b3);
            }
        }
        __syncthreads();
    }

    // epilogue: bias (+relu), scatter to per-pair row
#pragma unroll
    for (int i = 0; i < TM; i++) {
        int gmr = m0 + tr * TM + i;
        if (gmr >= count) continue;
        int ent = list[gmr];
        float* orow;
        if (MODE == 1) orow = g_h + (size_t)ent * HDIM + n0 + tc * TN;
        else           orow = g_y + (size_t)ent * DDIM + n0 + tc * TN;
        float ov[8];
#pragma unroll
        for (int j = 0; j < 4; j++) {
            float2 p = unpack2(acc[i][j]);
            ov[2 * j] = p.x;
            ov[2 * j + 1] = p.y;
        }
#pragma unroll
        for (int j = 0; j < 8; j++) {
            float v = ov[j] + bias[n0 + tc * TN + j];
            if (MODE == 1) v = fmaxf(v, 0.0f);
            ov[j] = v;
        }
        *(float4*)(orow)     = make_float4(ov[0], ov[1], ov[2], ov[3]);
        *(float4*)(orow + 4) = make_float4(ov[4], ov[5], ov[6], ov[7]);
    }
}

// ---------------- combine ----------------
__global__ void combine_kernel(float* __restrict__ out) {
    int idx = blockIdx.x * blockDim.x + threadIdx.x;  // over NTOK*DDIM/4
    if (idx >= NTOK * DDIM / 4) return;
    int t  = idx / (DDIM / 4);
    int d4 = idx % (DDIM / 4);
    const float4* y0 = (const float4*)(g_y + (size_t)(2 * t) * DDIM);
    float4 v = y0[d4];
    if (g_v1[t]) {
        const float4* y1 = (const float4*)(g_y + (size_t)(2 * t + 1) * DDIM);
        float4 w = y1[d4];
        v.x += w.x; v.y += w.y; v.z += w.z; v.w += w.w;
    }
    v.x *= 0.5f; v.y *= 0.5f; v.z *= 0.5f; v.w *= 0.5f;
    ((float4*)out)[idx] = v;
}

// ---------------- launch ----------------
extern "C" void kernel_launch(void* const* d_in, const int* in_sizes, int n_in,
                              void* d_out, int out_size) {
    const float* x  = (const float*)d_in[0];
    const int*   aw = (const int*)d_in[1];   // assign: int32 or int64 (detected)
    const float* W1 = (const float*)d_in[2];
    const float* b1 = (const float*)d_in[3];
    const float* W2 = (const float*)d_in[4];
    const float* b2 = (const float*)d_in[5];
    float* out = (float*)d_out;

    prep_kernel<<<1, 256>>>(aw);
    route_kernel<<<NTOK / 256, 256>>>(aw);
    moe_gemm<1><<<dim3(HDIM / BN, NTOK / BM, NEXP), 256>>>(x, W1, b1);
    moe_gemm<2><<<dim3(DDIM / BN, NTOK / BM, NEXP), 256>>>(nullptr, W2, b2);
    combine_kernel<<<(NTOK * DDIM / 4) / 256, 256>>>(out);
}

// round 3
// speedup vs baseline: 2.8626x; 2.8626x over previous
#include <cuda_runtime.h>
#include <stdint.h>

#define NTOK 16384
#define DDIM 512
#define HDIM 2048
#define NEXP 8
#define NPAIR (NTOK * 2)

// ---------------- device scratch (allocation-free) ----------------
__device__ int g_count[NEXP];
__device__ int g_base[NEXP];
__device__ int g_i64;
__device__ int g_list[NEXP * NTOK];            // entries: token*2 + slot
__device__ unsigned char g_v1[NTOK];
__device__ float g_xc[(size_t)NTOK * DDIM];    // tf32-rounded x
__device__ float g_W1t[(size_t)NEXP * DDIM * HDIM];  // [E][H][D] K-major
__device__ float g_W2t[(size_t)NEXP * DDIM * HDIM];  // [E][D][H] K-major
__device__ float g_h[((size_t)NPAIR + 128) * HDIM];  // compacted hidden
__device__ float g_y[(size_t)NPAIR * DDIM];

// ---------------- helpers ----------------
__device__ __forceinline__ uint32_t smem_to_u32(const void* p) {
    uint32_t a;
    asm("{ .reg .u64 t; cvta.to.shared.u64 t, %1; cvt.u32.u64 %0, t; }"
        : "=r"(a) : "l"(p));
    return a;
}
__device__ __forceinline__ float totf32(float f) {
    uint32_t u;
    asm("cvt.rna.tf32.f32 %0, %1;" : "=r"(u) : "f"(f));
    return __uint_as_float(u);
}
#define CP_ASYNC16(saddr, gptr) \
    asm volatile("cp.async.cg.shared.global [%0], [%1], 16;" :: "r"(saddr), "l"(gptr))
#define CP_COMMIT() asm volatile("cp.async.commit_group;" ::: "memory")
#define CP_WAIT1() asm volatile("cp.async.wait_group 1;" ::: "memory")

__device__ __forceinline__ void mma_tf32(float* c, const uint32_t* a, const uint32_t* b) {
    asm volatile(
        "mma.sync.aligned.m16n8k8.row.col.f32.tf32.tf32.f32 "
        "{%0,%1,%2,%3}, {%4,%5,%6,%7}, {%8,%9}, {%0,%1,%2,%3};"
        : "+f"(c[0]), "+f"(c[1]), "+f"(c[2]), "+f"(c[3])
        : "r"(a[0]), "r"(a[1]), "r"(a[2]), "r"(a[3]), "r"(b[0]), "r"(b[1]));
}

// ---------------- routing ----------------
__global__ void prep_kernel(const int* __restrict__ aw) {
    __shared__ int nz;
    if (threadIdx.x == 0) nz = 0;
    __syncthreads();
    if (threadIdx.x < 64)
        if (aw[2 * threadIdx.x + 1] != 0) atomicOr(&nz, 1);
    __syncthreads();
    if (threadIdx.x < NEXP) g_count[threadIdx.x] = 0;
    if (threadIdx.x == 0) g_i64 = (nz == 0) ? 1 : 0;
}

__global__ void route_kernel(const int* __restrict__ aw) {
    int t = blockIdx.x * blockDim.x + threadIdx.x;
    if (t >= NTOK) return;
    int e0, e1;
    if (g_i64) { e0 = aw[4 * t]; e1 = aw[4 * t + 2]; }
    else       { e0 = aw[2 * t]; e1 = aw[2 * t + 1]; }
    int p = atomicAdd(&g_count[e0], 1);
    g_list[e0 * NTOK + p] = 2 * t;
    int v1 = (e1 != e0) ? 1 : 0;
    g_v1[t] = (unsigned char)v1;
    if (v1) {
        p = atomicAdd(&g_count[e1], 1);
        g_list[e1 * NTOK + p] = 2 * t + 1;
    }
}

__global__ void base_kernel() {
    if (threadIdx.x == 0) {
        int s = 0;
        for (int e = 0; e < NEXP; e++) { g_base[e] = s; s += g_count[e]; }
    }
}

// ---------------- input rounding / weight transpose ----------------
__global__ void xconv_kernel(const float* __restrict__ x) {
    size_t i = (size_t)blockIdx.x * blockDim.x + threadIdx.x;
    float4 v = ((const float4*)x)[i];
    v.x = totf32(v.x); v.y = totf32(v.y); v.z = totf32(v.z); v.w = totf32(v.w);
    ((float4*)g_xc)[i] = v;
}

// in: [E][R][C] -> out: [E][C][R], tf32-rounded
__global__ void transpose_kernel(const float* __restrict__ in, int R, int C, int which) {
    __shared__ float t[32][33];
    float* out = which ? g_W2t : g_W1t;
    int e = blockIdx.z;
    const float* I = in + (size_t)e * R * C;
    float* O = out + (size_t)e * R * C;
    int c0 = blockIdx.x * 32, r0 = blockIdx.y * 32;
    int tx = threadIdx.x, ty = threadIdx.y;
#pragma unroll
    for (int j = 0; j < 32; j += 8)
        t[ty + j][tx] = totf32(I[(size_t)(r0 + ty + j) * C + c0 + tx]);
    __syncthreads();
#pragma unroll
    for (int j = 0; j < 32; j += 8)
        O[(size_t)(c0 + ty + j) * R + r0 + tx] = t[tx][ty + j];
}

// ---------------- tf32 mma.sync gather-GEMM ----------------
// CTA tile 128x128, BK=32, 2-stage cp.async double buffer.
// smem rows padded: stride 36 floats (144B, 16B-aligned) -> conflict-free LDS.
#define ASTRIDE 36
#define ABUF (128 * ASTRIDE)            // floats per stage per operand
#define ABUFBYTES (ABUF * 4)            // 18432
#define SMEM_BYTES (4 * ABUFBYTES)      // A0,A1,B0,B1 = 73728

// MODE 1: h = relu(xc @ W1t^T + b1)  KD=512,  ND=2048, out rows compact
// MODE 2: y = h @ W2t^T + b2         KD=2048, ND=512,  out rows scattered by list
template <int MODE>
__global__ __launch_bounds__(256, 1) void moe_mma(const float* __restrict__ biasAll) {
    constexpr int KD = (MODE == 1) ? DDIM : HDIM;
    constexpr int ND = (MODE == 1) ? HDIM : DDIM;
    constexpr int NS = KD / 32;

    const int e = blockIdx.z;
    const int count = g_count[e];
    const int m0 = blockIdx.y * 128;
    if (m0 >= count) return;
    const int n0 = blockIdx.x * 128;
    const int baseE = g_base[e];
    const float* __restrict__ W = (MODE == 1 ? g_W1t : g_W2t) + (size_t)e * KD * ND;
    const float* __restrict__ bias = biasAll + e * ND;
    const int* __restrict__ list = g_list + e * NTOK;

    extern __shared__ float smf[];
    const uint32_t sbase = smem_to_u32(smf);

    const int tid = threadIdx.x;
    const int wid = tid >> 5, lid = tid & 31;
    const int wm = wid >> 2, wn = wid & 3;         // warp grid 2(M) x 4(N)
    const int g = lid >> 2, tg = lid & 3;

    // ---- cp.async source/dest mapping: 8 x 16B chunks per thread per stage
    const int rA = tid >> 3;       // base row 0..31
    const int c16 = tid & 7;       // 16B chunk within 128B row
    const float* asrc[4];
    const float* bsrc[4];
    uint32_t aoff[4], boff[4];
#pragma unroll
    for (int j = 0; j < 4; j++) {
        int r = rA + 32 * j;
        int gm = m0 + r;
        if (gm >= count) gm = count - 1;
        const float* Ar;
        if (MODE == 1) Ar = g_xc + (size_t)(list[gm] >> 1) * DDIM;
        else           Ar = g_h + (size_t)(baseE + gm) * HDIM;
        asrc[j] = Ar + c16 * 4;
        aoff[j] = sbase + (uint32_t)(r * ASTRIDE + c16 * 4) * 4;
        bsrc[j] = W + (size_t)(n0 + r) * KD + c16 * 4;
        boff[j] = sbase + (uint32_t)(2 * ABUF + r * ASTRIDE + c16 * 4) * 4;
    }

    float acc[4][4][4];
#pragma unroll
    for (int i = 0; i < 4; i++)
#pragma unroll
        for (int j = 0; j < 4; j++)
#pragma unroll
            for (int q = 0; q < 4; q++) acc[i][j][q] = 0.f;

    auto load_stage = [&](int s) {
        const uint32_t bufo = (uint32_t)(s & 1) * ABUFBYTES;
        const int k0 = s * 32;
#pragma unroll
        for (int j = 0; j < 4; j++) {
            CP_ASYNC16(aoff[j] + bufo, asrc[j] + k0);
            CP_ASYNC16(boff[j] + bufo, bsrc[j] + k0);
        }
    };

    load_stage(0);
    CP_COMMIT();

    for (int s = 0; s < NS; s++) {
        if (s + 1 < NS) load_stage(s + 1);
        CP_COMMIT();
        CP_WAIT1();
        __syncthreads();

        const float* As = smf + (s & 1) * ABUF;
        const float* Bs = smf + 2 * ABUF + (s & 1) * ABUF;
#pragma unroll
        for (int ks = 0; ks < 4; ks++) {
            const int k0 = ks * 8;
            uint32_t a[4][4], b[4][2];
#pragma unroll
            for (int i = 0; i < 4; i++) {
                int r = wm * 64 + i * 16 + g;
                a[i][0] = __float_as_uint(As[r * ASTRIDE + k0 + tg]);
                a[i][1] = __float_as_uint(As[(r + 8) * ASTRIDE + k0 + tg]);
                a[i][2] = __float_as_uint(As[r * ASTRIDE + k0 + tg + 4]);
                a[i][3] = __float_as_uint(As[(r + 8) * ASTRIDE + k0 + tg + 4]);
            }
#pragma unroll
            for (int j = 0; j < 4; j++) {
                int n = wn * 32 + j * 8 + g;
                b[j][0] = __float_as_uint(Bs[n * ASTRIDE + k0 + tg]);
                b[j][1] = __float_as_uint(Bs[n * ASTRIDE + k0 + tg + 4]);
            }
#pragma unroll
            for (int i = 0; i < 4; i++)
#pragma unroll
                for (int j = 0; j < 4; j++) mma_tf32(acc[i][j], a[i], b[j]);
        }
        __syncthreads();
    }

    // ---- epilogue: bias (+relu(+tf32 re-round)), scatter per mma row layout
#pragma unroll
    for (int i = 0; i < 4; i++) {
#pragma unroll
        for (int half = 0; half < 2; half++) {
            int gm = m0 + wm * 64 + i * 16 + half * 8 + g;
            if (gm >= count) continue;
            float* orow;
            if (MODE == 1) orow = g_h + (size_t)(baseE + gm) * HDIM + n0;
            else           { int ent = list[gm]; orow = g_y + (size_t)ent * DDIM + n0; }
#pragma unroll
            for (int j = 0; j < 4; j++) {
                int col = wn * 32 + j * 8 + tg * 2;
                float2 bv = *(const float2*)(bias + n0 + col);
                float v0 = acc[i][j][2 * half + 0] + bv.x;
                float v1 = acc[i][j][2 * half + 1] + bv.y;
                if (MODE == 1) {
                    v0 = totf32(fmaxf(v0, 0.f));
                    v1 = totf32(fmaxf(v1, 0.f));
                }
                *(float2*)(orow + col) = make_float2(v0, v1);
            }
        }
    }
}

// ---------------- combine ----------------
__global__ void combine_kernel(float* __restrict__ out) {
    int idx = blockIdx.x * blockDim.x + threadIdx.x;
    if (idx >= NTOK * DDIM / 4) return;
    int t = idx / (DDIM / 4);
    int d4 = idx % (DDIM / 4);
    float4 v = ((const float4*)(g_y + (size_t)(2 * t) * DDIM))[d4];
    if (g_v1[t]) {
        float4 w = ((const float4*)(g_y + (size_t)(2 * t + 1) * DDIM))[d4];
        v.x += w.x; v.y += w.y; v.z += w.z; v.w += w.w;
    }
    v.x *= 0.5f; v.y *= 0.5f; v.z *= 0.5f; v.w *= 0.5f;
    ((float4*)out)[idx] = v;
}

// ---------------- launch ----------------
extern "C" void kernel_launch(void* const* d_in, const int* in_sizes, int n_in,
                              void* d_out, int out_size) {
    const float* x  = (const float*)d_in[0];
    const int*   aw = (const int*)d_in[1];
    const float* W1 = (const float*)d_in[2];
    const float* b1 = (const float*)d_in[3];
    const float* W2 = (const float*)d_in[4];
    const float* b2 = (const float*)d_in[5];
    float* out = (float*)d_out;

    cudaFuncSetAttribute(moe_mma<1>, cudaFuncAttributeMaxDynamicSharedMemorySize, SMEM_BYTES);
    cudaFuncSetAttribute(moe_mma<2>, cudaFuncAttributeMaxDynamicSharedMemorySize, SMEM_BYTES);

    prep_kernel<<<1, 256>>>(aw);
    route_kernel<<<NTOK / 256, 256>>>(aw);
    base_kernel<<<1, 32>>>();
    xconv_kernel<<<(NTOK * DDIM / 4) / 256, 256>>>(x);
    transpose_kernel<<<dim3(HDIM / 32, DDIM / 32, NEXP), dim3(32, 8)>>>(W1, DDIM, HDIM, 0);
    transpose_kernel<<<dim3(DDIM / 32, HDIM / 32, NEXP), dim3(32, 8)>>>(W2, HDIM, DDIM, 1);
    moe_mma<1><<<dim3(HDIM / 128, NTOK / 128, NEXP), 256, SMEM_BYTES>>>(b1);
    moe_mma<2><<<dim3(DDIM / 128, NTOK / 128, NEXP), 256, SMEM_BYTES>>>(b2);
    combine_kernel<<<(NTOK * DDIM / 4) / 256, 256>>>(out);
}

// round 4
// speedup vs baseline: 3.7533x; 1.3111x over previous
#include <cuda_runtime.h>
#include <stdint.h>

#define NTOK 16384
#define DDIM 512
#define HDIM 2048
#define NEXP 8
#define NPAIR (NTOK * 2)

// ---------------- device scratch (allocation-free) ----------------
__device__ int g_count[NEXP];
__device__ int g_base[NEXP];
__device__ int g_i64;
__device__ int g_list[NEXP * NTOK];            // entries: token*2 + slot
__device__ unsigned char g_v1[NTOK];
__device__ float g_xc[(size_t)NTOK * DDIM];    // tf32-rounded x
__device__ float g_W1t[(size_t)NEXP * DDIM * HDIM];  // [E][H][D] K-major
__device__ float g_W2t[(size_t)NEXP * DDIM * HDIM];  // [E][D][H] K-major
__device__ float g_h[((size_t)NPAIR + 128) * HDIM];  // compacted hidden
__device__ float g_y[(size_t)NPAIR * DDIM];

// ---------------- helpers ----------------
__device__ __forceinline__ uint32_t smem_to_u32(const void* p) {
    uint32_t a;
    asm("{ .reg .u64 t; cvta.to.shared.u64 t, %1; cvt.u32.u64 %0, t; }"
        : "=r"(a) : "l"(p));
    return a;
}
__device__ __forceinline__ float totf32(float f) {
    uint32_t u;
    asm("cvt.rna.tf32.f32 %0, %1;" : "=r"(u) : "f"(f));
    return __uint_as_float(u);
}
#define CP_ASYNC16(saddr, gptr) \
    asm volatile("cp.async.cg.shared.global [%0], [%1], 16;" :: "r"(saddr), "l"(gptr))
#define CP_COMMIT() asm volatile("cp.async.commit_group;" ::: "memory")
#define CP_WAIT2() asm volatile("cp.async.wait_group 2;" ::: "memory")

__device__ __forceinline__ void mma_tf32(float* c, const uint32_t* a, const uint32_t* b) {
    asm volatile(
        "mma.sync.aligned.m16n8k8.row.col.f32.tf32.tf32.f32 "
        "{%0,%1,%2,%3}, {%4,%5,%6,%7}, {%8,%9}, {%0,%1,%2,%3};"
        : "+f"(c[0]), "+f"(c[1]), "+f"(c[2]), "+f"(c[3])
        : "r"(a[0]), "r"(a[1]), "r"(a[2]), "r"(a[3]), "r"(b[0]), "r"(b[1]));
}
#define LDSM_X4(r0, r1, r2, r3, addr) \
    asm volatile("ldmatrix.sync.aligned.x4.m8n8.shared.b16 {%0,%1,%2,%3}, [%4];" \
                 : "=r"(r0), "=r"(r1), "=r"(r2), "=r"(r3) : "r"(addr))

// ---------------- routing ----------------
__global__ void prep_kernel(const int* __restrict__ aw) {
    __shared__ int nz;
    if (threadIdx.x == 0) nz = 0;
    __syncthreads();
    if (threadIdx.x < 64)
        if (aw[2 * threadIdx.x + 1] != 0) atomicOr(&nz, 1);
    __syncthreads();
    if (threadIdx.x < NEXP) g_count[threadIdx.x] = 0;
    if (threadIdx.x == 0) g_i64 = (nz == 0) ? 1 : 0;
}

__global__ void route_kernel(const int* __restrict__ aw) {
    int t = blockIdx.x * blockDim.x + threadIdx.x;
    if (t >= NTOK) return;
    int e0, e1;
    if (g_i64) { e0 = aw[4 * t]; e1 = aw[4 * t + 2]; }
    else       { e0 = aw[2 * t]; e1 = aw[2 * t + 1]; }
    int p = atomicAdd(&g_count[e0], 1);
    g_list[e0 * NTOK + p] = 2 * t;
    int v1 = (e1 != e0) ? 1 : 0;
    g_v1[t] = (unsigned char)v1;
    if (v1) {
        p = atomicAdd(&g_count[e1], 1);
        g_list[e1 * NTOK + p] = 2 * t + 1;
    }
}

__global__ void base_kernel() {
    if (threadIdx.x == 0) {
        int s = 0;
        for (int e = 0; e < NEXP; e++) { g_base[e] = s; s += g_count[e]; }
    }
}

// ---------------- input rounding / weight transpose ----------------
__global__ void xconv_kernel(const float* __restrict__ x) {
    size_t i = (size_t)blockIdx.x * blockDim.x + threadIdx.x;
    float4 v = ((const float4*)x)[i];
    v.x = totf32(v.x); v.y = totf32(v.y); v.z = totf32(v.z); v.w = totf32(v.w);
    ((float4*)g_xc)[i] = v;
}

// in: [E][R][C] -> out: [E][C][R], tf32-rounded
__global__ void transpose_kernel(const float* __restrict__ in, int R, int C, int which) {
    __shared__ float t[32][33];
    float* out = which ? g_W2t : g_W1t;
    int e = blockIdx.z;
    const float* I = in + (size_t)e * R * C;
    float* O = out + (size_t)e * R * C;
    int c0 = blockIdx.x * 32, r0 = blockIdx.y * 32;
    int tx = threadIdx.x, ty = threadIdx.y;
#pragma unroll
    for (int j = 0; j < 32; j += 8)
        t[ty + j][tx] = totf32(I[(size_t)(r0 + ty + j) * C + c0 + tx]);
    __syncthreads();
#pragma unroll
    for (int j = 0; j < 32; j += 8)
        O[(size_t)(c0 + ty + j) * R + r0 + tx] = t[tx][ty + j];
}

// ---------------- tf32 mma.sync gather-GEMM ----------------
// CTA tile 128x128, BK=32, 3-stage cp.async ring, ldmatrix fragment loads.
// smem rows padded: stride 36 floats (144B) -> conflict-free LDS/LDSM.
#define ASTRIDE 36
#define ABUF (128 * ASTRIDE)            // floats per stage per operand
#define ABUFBYTES (ABUF * 4)            // 18432
#define NSTG 3
#define SMEM_BYTES (2 * NSTG * ABUFBYTES)   // 110592

// MODE 1: h = relu(xc @ W1t^T + b1)  KD=512,  ND=2048, out rows compact
// MODE 2: y = h @ W2t^T + b2         KD=2048, ND=512,  out rows scattered by list
template <int MODE>
__global__ __launch_bounds__(256, 2) void moe_mma(const float* __restrict__ biasAll) {
    constexpr int KD = (MODE == 1) ? DDIM : HDIM;
    constexpr int ND = (MODE == 1) ? HDIM : DDIM;
    constexpr int NS = KD / 32;

    const int e = blockIdx.z;
    const int count = g_count[e];
    const int m0 = blockIdx.y * 128;
    if (m0 >= count) return;
    const int n0 = blockIdx.x * 128;
    const int baseE = g_base[e];
    const float* __restrict__ W = (MODE == 1 ? g_W1t : g_W2t) + (size_t)e * KD * ND;
    const float* __restrict__ bias = biasAll + e * ND;
    const int* __restrict__ list = g_list + e * NTOK;

    extern __shared__ float smf[];
    const uint32_t sbase = smem_to_u32(smf);

    const int tid = threadIdx.x;
    const int wid = tid >> 5, lid = tid & 31;
    const int wm = wid >> 2, wn = wid & 3;         // warp grid 2(M) x 4(N)
    const int g = lid >> 2, tg = lid & 3;

    // ---- cp.async mapping: 8 x 16B chunks per thread per stage
    const int rA = tid >> 3;       // base row 0..31
    const int c16 = tid & 7;       // 16B chunk within 128B row
    const float* asrc[4];
    const float* bsrc[4];
    uint32_t aoff[4], boff[4];
#pragma unroll
    for (int j = 0; j < 4; j++) {
        int r = rA + 32 * j;
        int gm = m0 + r;
        if (gm >= count) gm = count - 1;
        const float* Ar;
        if (MODE == 1) Ar = g_xc + (size_t)(list[gm] >> 1) * DDIM;
        else           Ar = g_h + (size_t)(baseE + gm) * HDIM;
        asrc[j] = Ar + c16 * 4;
        aoff[j] = sbase + (uint32_t)(r * ASTRIDE + c16 * 4) * 4;
        bsrc[j] = W + (size_t)(n0 + r) * KD + c16 * 4;
        boff[j] = sbase + (uint32_t)(NSTG * ABUF + r * ASTRIDE + c16 * 4) * 4;
    }

    // ---- ldmatrix per-thread addresses (byte offsets within a stage buffer)
    // A tile i (16 rows): tiles (r,k0),(r+8,k0),(r,k0+4),(r+8,k0+4)
    uint32_t lma[4];
#pragma unroll
    for (int i = 0; i < 4; i++) {
        int row = wm * 64 + i * 16 + ((lid >> 3) & 1) * 8 + (lid & 7);
        lma[i] = (uint32_t)(row * ASTRIDE + ((lid >> 4) & 1) * 4) * 4;
    }
    // B pair p (n-tiles 2p,2p+1): tiles (n0p,k0),(n0p,k0+4),(n1p,k0),(n1p,k0+4)
    uint32_t lmb[2];
#pragma unroll
    for (int p = 0; p < 2; p++) {
        int row = wn * 32 + (p * 2 + ((lid >> 4) & 1)) * 8 + (lid & 7);
        lmb[p] = (uint32_t)(row * ASTRIDE + ((lid >> 3) & 1) * 4) * 4;
    }

    float acc[4][4][4];
#pragma unroll
    for (int i = 0; i < 4; i++)
#pragma unroll
        for (int j = 0; j < 4; j++)
#pragma unroll
            for (int q = 0; q < 4; q++) acc[i][j][q] = 0.f;

    auto load_stage = [&](int s) {
        const uint32_t bufo = (uint32_t)(s % NSTG) * ABUFBYTES;
        const int k0 = s * 32;
#pragma unroll
        for (int j = 0; j < 4; j++) {
            CP_ASYNC16(aoff[j] + bufo, asrc[j] + k0);
            CP_ASYNC16(boff[j] + bufo, bsrc[j] + k0);
        }
    };

    load_stage(0); CP_COMMIT();
    load_stage(1); CP_COMMIT();

    for (int s = 0; s < NS; s++) {
        if (s + 2 < NS) load_stage(s + 2);
        CP_COMMIT();
        CP_WAIT2();
        __syncthreads();

        const uint32_t sa = sbase + (uint32_t)(s % NSTG) * ABUFBYTES;
        const uint32_t sb = sa + (uint32_t)NSTG * ABUFBYTES;
#pragma unroll
        for (int ks = 0; ks < 4; ks++) {
            const uint32_t kb = (uint32_t)ks * 32;  // 8 floats
            uint32_t a[4][4], b[2][4];
#pragma unroll
            for (int i = 0; i < 4; i++)
                LDSM_X4(a[i][0], a[i][1], a[i][2], a[i][3], sa + lma[i] + kb);
#pragma unroll
            for (int p = 0; p < 2; p++)
                LDSM_X4(b[p][0], b[p][1], b[p][2], b[p][3], sb + lmb[p] + kb);
#pragma unroll
            for (int i = 0; i < 4; i++)
#pragma unroll
                for (int j = 0; j < 4; j++)
                    mma_tf32(acc[i][j], a[i], &b[j >> 1][(j & 1) * 2]);
        }
        __syncthreads();
    }

    // ---- epilogue: bias (+relu(+tf32 re-round)), scatter per mma row layout
#pragma unroll
    for (int i = 0; i < 4; i++) {
#pragma unroll
        for (int half = 0; half < 2; half++) {
            int gm = m0 + wm * 64 + i * 16 + half * 8 + g;
            if (gm >= count) continue;
            float* orow;
            if (MODE == 1) orow = g_h + (size_t)(baseE + gm) * HDIM + n0;
            else           { int ent = list[gm]; orow = g_y + (size_t)ent * DDIM + n0; }
#pragma unroll
            for (int j = 0; j < 4; j++) {
                int col = wn * 32 + j * 8 + tg * 2;
                float2 bv = *(const float2*)(bias + n0 + col);
                float v0 = acc[i][j][2 * half + 0] + bv.x;
                float v1 = acc[i][j][2 * half + 1] + bv.y;
                if (MODE == 1) {
                    v0 = totf32(fmaxf(v0, 0.f));
                    v1 = totf32(fmaxf(v1, 0.f));
                }
                *(float2*)(orow + col) = make_float2(v0, v1);
            }
        }
    }
}

// ---------------- combine ----------------
__global__ void combine_kernel(float* __restrict__ out) {
    int idx = blockIdx.x * blockDim.x + threadIdx.x;
    if (idx >= NTOK * DDIM / 4) return;
    int t = idx / (DDIM / 4);
    int d4 = idx % (DDIM / 4);
    float4 v = ((const float4*)(g_y + (size_t)(2 * t) * DDIM))[d4];
    if (g_v1[t]) {
        float4 w = ((const float4*)(g_y + (size_t)(2 * t + 1) * DDIM))[d4];
        v.x += w.x; v.y += w.y; v.z += w.z; v.w += w.w;
    }
    v.x *= 0.5f; v.y *= 0.5f; v.z *= 0.5f; v.w *= 0.5f;
    ((float4*)out)[idx] = v;
}

// ---------------- launch ----------------
extern "C" void kernel_launch(void* const* d_in, const int* in_sizes, int n_in,
                              void* d_out, int out_size) {
    const float* x  = (const float*)d_in[0];
    const int*   aw = (const int*)d_in[1];
    const float* W1 = (const float*)d_in[2];
    const float* b1 = (const float*)d_in[3];
    const float* W2 = (const float*)d_in[4];
    const float* b2 = (const float*)d_in[5];
    float* out = (float*)d_out;

    cudaFuncSetAttribute(moe_mma<1>, cudaFuncAttributeMaxDynamicSharedMemorySize, SMEM_BYTES);
    cudaFuncSetAttribute(moe_mma<2>, cudaFuncAttributeMaxDynamicSharedMemorySize, SMEM_BYTES);

    prep_kernel<<<1, 256>>>(aw);
    route_kernel<<<NTOK / 256, 256>>>(aw);
    base_kernel<<<1, 32>>>();
    xconv_kernel<<<(NTOK * DDIM / 4) / 256, 256>>>(x);
    transpose_kernel<<<dim3(HDIM / 32, DDIM / 32, NEXP), dim3(32, 8)>>>(W1, DDIM, HDIM, 0);
    transpose_kernel<<<dim3(DDIM / 32, HDIM / 32, NEXP), dim3(32, 8)>>>(W2, HDIM, DDIM, 1);
    moe_mma<1><<<dim3(HDIM / 128, NTOK / 128, NEXP), 256, SMEM_BYTES>>>(b1);
    moe_mma<2><<<dim3(DDIM / 128, NTOK / 128, NEXP), 256, SMEM_BYTES>>>(b2);
    combine_kernel<<<(NTOK * DDIM / 4) / 256, 256>>>(out);
}